// round 2
// baseline (speedup 1.0000x reference)
#include <cuda_runtime.h>
#include <cuda_fp16.h>
#include <mma.h>

using namespace nvcuda;

// Problem constants
#define M_TOK   4096
#define K_IN    4096
#define N_OUT   11008
#define GROUPSZ 128

// Scratch (device globals; no allocation allowed):
//   dequantized weights [K_IN, N_OUT] fp16 (~90 MB)
//   x converted to fp16 [M_TOK, K_IN]  (~34 MB)
__device__ __half g_Wdeq[(size_t)K_IN * N_OUT];
__device__ __half g_Xh[(size_t)M_TOK * K_IN];

// ---------------------------------------------------------------------------
// Kernel 0: convert x f32 -> f16 (harness materializes jax float16 as float32)
// ---------------------------------------------------------------------------
__global__ void convert_x_kernel(const float* __restrict__ x)
{
    size_t i = ((size_t)blockIdx.x * blockDim.x + threadIdx.x) * 4;
    if (i >= (size_t)M_TOK * K_IN) return;
    float4 v = *(const float4*)(x + i);
    __half2 lo = __floats2half2_rn(v.x, v.y);
    __half2 hi = __floats2half2_rn(v.z, v.w);
    *(__half2*)(g_Xh + i)     = lo;
    *(__half2*)(g_Xh + i + 2) = hi;
}

// ---------------------------------------------------------------------------
// Kernel 1: GPTQ 4-bit dequant
// qweight: [K_IN/8, N_OUT] int32, nibbles pack K (8 consecutive k per word)
// qzeros : [G, N_OUT/8]   int32, nibbles pack N (8 consecutive o per word)
// scales : [G, N_OUT]     f32 (fp16 values, stored as f32 by harness)
// W[k][o] = scales[g][o] * ( ((qw[k/8][o]>>(4*(k%8)))&15) - (((qz[g][o/8]>>(4*(o%8)))&15)+1) )
// ---------------------------------------------------------------------------
__global__ void dequant_kernel(const int* __restrict__ qweight,
                               const int* __restrict__ qzeros,
                               const float* __restrict__ scales,
                               const int* __restrict__ g_idx)
{
    int o  = blockIdx.x * blockDim.x + threadIdx.x;
    int kp = blockIdx.y;                 // packed row index, 0..K_IN/8-1
    if (o >= N_OUT) return;

    int k0 = kp * 8;
    int g  = g_idx[k0];                  // GROUPSZ=128 is a multiple of 8 -> same group for all 8

    unsigned qwv = (unsigned)qweight[(size_t)kp * N_OUT + o];
    unsigned zwv = (unsigned)qzeros[(size_t)g * (N_OUT / 8) + (o >> 3)];
    int z   = (int)((zwv >> ((o & 7) * 4)) & 15u) + 1;
    float s = scales[(size_t)g * N_OUT + o];

    #pragma unroll
    for (int j = 0; j < 8; j++) {
        int q = (int)((qwv >> (4 * j)) & 15u);
        g_Wdeq[(size_t)(k0 + j) * N_OUT + o] = __float2half(s * (float)(q - z));
    }
}

// ---------------------------------------------------------------------------
// Kernel 2: fp16 WMMA GEMM  C[M,N] = X[M,K] * W[K,N] + bias   (C, bias f32)
// Block tile: 64(M) x 128(N), BK=32. 8 warps (2x4), each warp 32x32 (2x2 frags).
// ---------------------------------------------------------------------------
#define BM 64
#define BN 128
#define BK 32

#define A_LD (BK + 8)    // 40, mult of 8
#define B_LD (BN + 8)    // 136, mult of 8
#define C_LD 36          // float staging, mult of 4

#define SMEM_BYTES 36864 // max(A+B tiles = 13824, epilogue = 8*32*36*4 = 36864)

__global__ __launch_bounds__(256, 2)
void gemm_kernel(const float* __restrict__ bias,
                 float* __restrict__ C)
{
    __shared__ __align__(16) unsigned char smem[SMEM_BYTES];
    __half* As = (__half*)smem;                       // [BM][A_LD]
    __half* Bs = (__half*)(smem + BM * A_LD * 2);     // [BK][B_LD]

    const int bn  = blockIdx.x * BN;
    const int bm  = blockIdx.y * BM;
    const int tid = threadIdx.x;
    const int warp = tid >> 5;
    const int lane = tid & 31;
    const int wm = (warp >> 2) * 32;   // 0 or 32
    const int wn = (warp & 3) * 32;    // 0,32,64,96

    wmma::fragment<wmma::accumulator, 16, 16, 16, float> acc[2][2];
    #pragma unroll
    for (int i = 0; i < 2; i++)
        #pragma unroll
        for (int j = 0; j < 2; j++)
            wmma::fill_fragment(acc[i][j], 0.0f);

    // A tile load mapping: 64x32 halves = 256 x int4 (one per thread)
    const int a_row  = tid >> 2;          // 0..63
    const int a_col8 = (tid & 3) * 8;     // 0,8,16,24
    // B tile load mapping: 32x128 halves = 512 x int4 (two per thread)
    const int b_row0  = tid >> 4;         // 0..15
    const int b_col8  = (tid & 15) * 8;   // 0..120

    const __half* Wd = g_Wdeq;
    const __half* Xh = g_Xh;

    for (int k0 = 0; k0 < K_IN; k0 += BK) {
        __syncthreads();
        // load A
        *(int4*)(As + a_row * A_LD + a_col8) =
            *(const int4*)(Xh + (size_t)(bm + a_row) * K_IN + k0 + a_col8);
        // load B (two row-halves per thread)
        *(int4*)(Bs + b_row0 * B_LD + b_col8) =
            *(const int4*)(Wd + (size_t)(k0 + b_row0) * N_OUT + bn + b_col8);
        *(int4*)(Bs + (b_row0 + 16) * B_LD + b_col8) =
            *(const int4*)(Wd + (size_t)(k0 + b_row0 + 16) * N_OUT + bn + b_col8);
        __syncthreads();

        #pragma unroll
        for (int kk = 0; kk < BK; kk += 16) {
            wmma::fragment<wmma::matrix_a, 16, 16, 16, __half, wmma::row_major> afrag[2];
            wmma::fragment<wmma::matrix_b, 16, 16, 16, __half, wmma::row_major> bfrag[2];
            #pragma unroll
            for (int i = 0; i < 2; i++)
                wmma::load_matrix_sync(afrag[i], As + (wm + i * 16) * A_LD + kk, A_LD);
            #pragma unroll
            for (int j = 0; j < 2; j++)
                wmma::load_matrix_sync(bfrag[j], Bs + kk * B_LD + wn + j * 16, B_LD);
            #pragma unroll
            for (int i = 0; i < 2; i++)
                #pragma unroll
                for (int j = 0; j < 2; j++)
                    wmma::mma_sync(acc[i][j], afrag[i], bfrag[j], acc[i][j]);
        }
    }

    // Epilogue: stage fp32 per-warp, add bias, write f32
    __syncthreads();
    float* Cw = (float*)smem + warp * 32 * C_LD;
    #pragma unroll
    for (int i = 0; i < 2; i++)
        #pragma unroll
        for (int j = 0; j < 2; j++)
            wmma::store_matrix_sync(Cw + (i * 16) * C_LD + j * 16, acc[i][j],
                                    C_LD, wmma::mem_row_major);
    __syncwarp();

    const float bval = bias[bn + wn + lane];
    #pragma unroll
    for (int r = 0; r < 32; r++) {
        float v = Cw[r * C_LD + lane] + bval;
        C[(size_t)(bm + wm + r) * N_OUT + bn + wn + lane] = v;
    }
}

// ---------------------------------------------------------------------------
// Launch
// Inputs (metadata order): x(f32), qweight(i32), qzeros(i32), scales(f32),
//                          g_idx(i32), bias(f32). Output: f32 [M_TOK, N_OUT].
// ---------------------------------------------------------------------------
extern "C" void kernel_launch(void* const* d_in, const int* in_sizes, int n_in,
                              void* d_out, int out_size)
{
    const float* x       = (const float*)d_in[0];
    const int*   qweight = (const int*)d_in[1];
    const int*   qzeros  = (const int*)d_in[2];
    const float* scales  = (const float*)d_in[3];
    const int*   g_idx   = (const int*)d_in[4];
    const float* bias    = (const float*)d_in[5];
    float* out = (float*)d_out;

    // 0) convert x to fp16
    {
        size_t n4 = (size_t)M_TOK * K_IN / 4;
        convert_x_kernel<<<(unsigned)((n4 + 255) / 256), 256>>>(x);
    }
    // 1) dequantize weights
    {
        dim3 grid((N_OUT + 255) / 256, K_IN / 8);
        dequant_kernel<<<grid, 256>>>(qweight, qzeros, scales, g_idx);
    }
    // 2) GEMM + bias
    {
        dim3 grid(N_OUT / BN, M_TOK / BM);
        gemm_kernel<<<grid, 256>>>(bias, out);
    }
}

// round 4
// speedup vs baseline: 1.9537x; 1.9537x over previous
#include <cuda_runtime.h>
#include <cuda_fp16.h>
#include <mma.h>
#include <cstdint>

using namespace nvcuda;

// ---------------------------------------------------------------------------
// Problem constants
// ---------------------------------------------------------------------------
#define M_TOK   4096
#define K_IN    4096
#define N_OUT   11008
#define GROUPSZ 128

// GEMM tiling
#define BM      128
#define BN      256
#define BK      32
#define NITER   (K_IN / BK)        // 128

#define A_LD    40                 // 32 + 8 pad (halves)
#define B_LD    264                // 256 + 8 pad (halves)
#define C_LD    68                 // 64 + 4 pad (floats), epilogue staging

#define A_STAGE_BYTES (BM * A_LD * 2)      // 10240
#define B_STAGE_BYTES (BK * B_LD * 2)      // 16896
#define SMEM_A0  0
#define SMEM_A1  (A_STAGE_BYTES)
#define SMEM_B0  (2 * A_STAGE_BYTES)
#define SMEM_B1  (2 * A_STAGE_BYTES + B_STAGE_BYTES)
#define SMEM_DYN (2 * A_STAGE_BYTES + 2 * B_STAGE_BYTES)   // 54272

// fp16 x scratch (no allocations allowed)
__device__ __half g_Xh[(size_t)M_TOK * K_IN];

// ---------------------------------------------------------------------------
// Kernel 0: convert x f32 -> f16 (harness materializes jax f16 as f32)
// ---------------------------------------------------------------------------
__global__ void convert_x_kernel(const float* __restrict__ x)
{
    size_t i = ((size_t)blockIdx.x * blockDim.x + threadIdx.x) * 4;
    if (i >= (size_t)M_TOK * K_IN) return;
    float4 v = *(const float4*)(x + i);
    *(__half2*)(g_Xh + i)     = __floats2half2_rn(v.x, v.y);
    *(__half2*)(g_Xh + i + 2) = __floats2half2_rn(v.z, v.w);
}

// ---------------------------------------------------------------------------
// cp.async helpers
// ---------------------------------------------------------------------------
__device__ __forceinline__ uint32_t smem_u32(const void* p) {
    uint32_t a;
    asm("{ .reg .u64 t; cvta.to.shared.u64 t, %1; cvt.u32.u64 %0, t; }"
        : "=r"(a) : "l"(p));
    return a;
}
__device__ __forceinline__ void cp_async16(uint32_t saddr, const void* gaddr) {
    asm volatile("cp.async.ca.shared.global [%0], [%1], 16;\n"
                 :: "r"(saddr), "l"(gaddr));
}
#define CP_COMMIT() asm volatile("cp.async.commit_group;\n" ::: "memory")
#define CP_WAIT0()  asm volatile("cp.async.wait_group 0;\n" ::: "memory")

// ---------------------------------------------------------------------------
// Fused 4-bit dequant + HMMA GEMM:  C[M,N] = X[M,K] * dequant(Q)[K,N] + bias
//
// qweight: [K/8, N] int32, nibbles pack K     (8 consecutive k per word)
// qzeros : [G, N/8] int32, nibbles pack N     (8 consecutive n per word)
// scales : [G, N] f32 (fp16 values)
//
// B tile [BK=32, BN=256] is dequantized in-kernel into SMEM each stage.
// Dequant uses fp16 magic numbers: fp16(0x6400|q) = 1024+q exactly, so
// (u - (1024+z)) * s reproduces fp16(scale) * fp16(q - z) bit-exactly.
// ---------------------------------------------------------------------------
__global__ void __launch_bounds__(256)
gemm_q4_kernel(const int* __restrict__ qweight,
               const int* __restrict__ qzeros,
               const float* __restrict__ scales,
               const float* __restrict__ bias,
               float* __restrict__ out)
{
    extern __shared__ __align__(16) char smem[];
    const uint32_t sbase = smem_u32(smem);

    const int tid  = threadIdx.x;
    const int warp = tid >> 5;
    const int lane = tid & 31;
    const int bm   = blockIdx.x * BM;   // M fastest: A + qweight stay L2-resident
    const int bn   = blockIdx.y * BN;

    // warp tile: 64x64.  warp grid 2(M) x 4(N)
    const int wm = (warp >> 2) * 64;
    const int wn = (warp & 3) * 64;

    const __half* Xb = g_Xh + (size_t)bm * K_IN;

    // ---- B dequant mapping: thread -> 2 adjacent N columns, 2 kp rows ----
    const int n0    = (tid & 127) * 2;      // 0,2,..,254
    const int rbase = (tid >> 7) * 2;       // kp rows {0,1} or {2,3} within stage
    const int o     = bn + n0;              // global N column (even)

    // ---- A cp.async mapping: 512 x 16B chunks, 2 per thread ----
    // chunk c: row = c>>2, colchunk = c&3 (8 halves each)

    wmma::fragment<wmma::accumulator, 16, 16, 16, float> acc[4][4];
    #pragma unroll
    for (int i = 0; i < 4; i++)
        #pragma unroll
        for (int j = 0; j < 4; j++)
            wmma::fill_fragment(acc[i][j], 0.0f);

    uint32_t breg[4];        // 2 kp rows x 2 cols of raw qweight
    uint32_t hb2[2];         // fp16x2 (1024+z0, 1024+z1) for the 2 cols? per col pair
    __half2  hs2;            // fp16x2 (s0, s1)

    auto ldg_b = [&](int ks) {
        const int* qw = qweight + (size_t)(ks * 4 + rbase) * N_OUT + o;
        breg[0] = (uint32_t)qw[0];
        breg[1] = (uint32_t)qw[1];
        breg[2] = (uint32_t)qw[N_OUT];
        breg[3] = (uint32_t)qw[N_OUT + 1];
    };
    auto ldg_consts = [&](int g) {
        uint32_t zw = (uint32_t)qzeros[(size_t)g * (N_OUT / 8) + (o >> 3)];
        uint32_t z0 = ((zw >> ((o & 7) * 4)) & 15u) + 1u;
        uint32_t z1 = ((zw >> ((o & 7) * 4 + 4)) & 15u) + 1u;
        hb2[0] = (0x6400u + z0) | ((0x6400u + z1) << 16);
        float s0 = scales[(size_t)g * N_OUT + o];
        float s1 = scales[(size_t)g * N_OUT + o + 1];
        hs2 = __halves2half2(__float2half_rn(s0), __float2half_rn(s1));
    };
    auto issue_a = [&](int ks, uint32_t abase) {
        const int k0 = ks * BK;
        #pragma unroll
        for (int i = 0; i < 2; i++) {
            int c = tid + 256 * i;
            int row = c >> 2, cc = c & 3;
            cp_async16(abase + (uint32_t)(row * A_LD + cc * 8) * 2,
                       Xb + (size_t)row * K_IN + k0 + cc * 8);
        }
    };
    auto store_b = [&](uint32_t bbase) {
        __half2 bias2 = *(__half2*)&hb2[0];
        #pragma unroll
        for (int r = 0; r < 2; r++) {
            uint32_t w0 = breg[r * 2 + 0];
            uint32_t w1 = breg[r * 2 + 1];
            int krow = (rbase + r) * 8;
            #pragma unroll
            for (int j = 0; j < 8; j++) {
                uint32_t u = 0x64006400u
                           | ((w0 >> (4 * j)) & 0xFu)
                           | (((w1 >> (4 * j)) & 0xFu) << 16);
                __half2 h = __hmul2(__hsub2(*(__half2*)&u, bias2), hs2);
                *(__half2*)(smem + bbase - sbase
                            + (uint32_t)((krow + j) * B_LD + n0) * 2) = h;
            }
        }
    };

    // ---- prologue: stage 0 ----
    issue_a(0, sbase + SMEM_A0);
    CP_COMMIT();
    ldg_b(0);
    ldg_consts(0);
    store_b(sbase + SMEM_B0);
    CP_WAIT0();
    __syncthreads();

    const uint32_t a_off[2] = {SMEM_A0, SMEM_A1};
    const uint32_t b_off[2] = {SMEM_B0, SMEM_B1};

    for (int ks = 0; ks < NITER; ks++) {
        const int buf = ks & 1;
        const int nxt = buf ^ 1;

        if (ks + 1 < NITER) {
            issue_a(ks + 1, sbase + a_off[nxt]);
            CP_COMMIT();
            ldg_b(ks + 1);
            if (((ks + 1) & 3) == 0)
                ldg_consts((ks + 1) >> 2);
        }

        // ---- compute on current buffers ----
        const __half* As = (const __half*)(smem + a_off[buf]);
        const __half* Bs = (const __half*)(smem + b_off[buf]);
        #pragma unroll
        for (int kk = 0; kk < BK; kk += 16) {
            wmma::fragment<wmma::matrix_a, 16, 16, 16, __half, wmma::row_major> af[4];
            #pragma unroll
            for (int i = 0; i < 4; i++)
                wmma::load_matrix_sync(af[i], As + (wm + i * 16) * A_LD + kk, A_LD);
            #pragma unroll
            for (int j = 0; j < 4; j++) {
                wmma::fragment<wmma::matrix_b, 16, 16, 16, __half, wmma::row_major> bf;
                wmma::load_matrix_sync(bf, Bs + kk * B_LD + wn + j * 16, B_LD);
                #pragma unroll
                for (int i = 0; i < 4; i++)
                    wmma::mma_sync(acc[i][j], af[i], bf, acc[i][j]);
            }
        }

        if (ks + 1 < NITER)
            store_b(sbase + b_off[nxt]);

        CP_WAIT0();
        __syncthreads();
    }

    // ---- epilogue: stage fp32 per warp (16x64 chunks), add bias, write ----
    __syncthreads();   // smem reuse
    float* fbuf = (float*)smem + warp * 16 * C_LD;
    const float* brow = bias + bn + wn;
    #pragma unroll
    for (int i = 0; i < 4; i++) {
        #pragma unroll
        for (int j = 0; j < 4; j++)
            wmma::store_matrix_sync(fbuf + j * 16, acc[i][j], C_LD, wmma::mem_row_major);
        __syncwarp();
        #pragma unroll
        for (int ii = 0; ii < 8; ii++) {
            int idx4 = lane + 32 * ii;          // 256 float4 = 16x64
            int row  = idx4 >> 4;
            int col  = (idx4 & 15) * 4;
            float4 v = *(float4*)(fbuf + row * C_LD + col);
            float4 b4 = *(const float4*)(brow + col);
            v.x += b4.x; v.y += b4.y; v.z += b4.z; v.w += b4.w;
            *(float4*)(out + (size_t)(bm + wm + i * 16 + row) * N_OUT + bn + wn + col) = v;
        }
        __syncwarp();
    }
}

// ---------------------------------------------------------------------------
// Launch.  Inputs: x(f32), qweight(i32), qzeros(i32), scales(f32), g_idx(i32),
//                  bias(f32).  Output f32 [M_TOK, N_OUT].
// ---------------------------------------------------------------------------
extern "C" void kernel_launch(void* const* d_in, const int* in_sizes, int n_in,
                              void* d_out, int out_size)
{
    const float* x       = (const float*)d_in[0];
    const int*   qweight = (const int*)d_in[1];
    const int*   qzeros  = (const int*)d_in[2];
    const float* scales  = (const float*)d_in[3];
    const float* bias    = (const float*)d_in[5];
    float* out = (float*)d_out;

    {
        size_t n4 = (size_t)M_TOK * K_IN / 4;
        convert_x_kernel<<<(unsigned)((n4 + 255) / 256), 256>>>(x);
    }
    {
        cudaFuncSetAttribute(gemm_q4_kernel,
                             cudaFuncAttributeMaxDynamicSharedMemorySize,
                             SMEM_DYN);
        dim3 grid(M_TOK / BM, N_OUT / BN);   // (32, 43), M fastest
        gemm_q4_kernel<<<grid, 256, SMEM_DYN>>>(qweight, qzeros, scales, bias, out);
    }
}

// round 5
// speedup vs baseline: 2.1296x; 1.0900x over previous
#include <cuda_runtime.h>
#include <cuda_fp16.h>
#include <mma.h>
#include <cstdint>

using namespace nvcuda;

// ---------------------------------------------------------------------------
// Problem constants
// ---------------------------------------------------------------------------
#define M_TOK   4096
#define K_IN    4096
#define N_OUT   11008
#define GROUPSZ 128

// GEMM tiling
#define BM      128
#define BN      256
#define BK      64
#define NITER   (K_IN / BK)        // 64

#define A_LD    72                 // 64 + 8 pad (halves): 144B row stride
#define B_LD    264                // 256 + 8 pad (halves): 528B row stride
#define C_LD    68                 // 64 + 4 pad (floats), epilogue staging

#define A_STAGE_BYTES (BM * A_LD * 2)      // 18432
#define B_STAGE_BYTES (BK * B_LD * 2)      // 33792
#define SMEM_A0  0
#define SMEM_A1  (A_STAGE_BYTES)
#define SMEM_B0  (2 * A_STAGE_BYTES)
#define SMEM_B1  (2 * A_STAGE_BYTES + B_STAGE_BYTES)
#define SMEM_DYN (2 * A_STAGE_BYTES + 2 * B_STAGE_BYTES)   // 104448

// fp16 x scratch (no allocations allowed)
__device__ __half g_Xh[(size_t)M_TOK * K_IN];

// ---------------------------------------------------------------------------
// Kernel 0: convert x f32 -> f16 (harness materializes jax f16 as f32)
// ---------------------------------------------------------------------------
__global__ void convert_x_kernel(const float* __restrict__ x)
{
    size_t i = ((size_t)blockIdx.x * blockDim.x + threadIdx.x) * 4;
    if (i >= (size_t)M_TOK * K_IN) return;
    float4 v = *(const float4*)(x + i);
    *(__half2*)(g_Xh + i)     = __floats2half2_rn(v.x, v.y);
    *(__half2*)(g_Xh + i + 2) = __floats2half2_rn(v.z, v.w);
}

// ---------------------------------------------------------------------------
// helpers
// ---------------------------------------------------------------------------
__device__ __forceinline__ uint32_t smem_u32(const void* p) {
    uint32_t a;
    asm("{ .reg .u64 t; cvta.to.shared.u64 t, %1; cvt.u32.u64 %0, t; }"
        : "=r"(a) : "l"(p));
    return a;
}
__device__ __forceinline__ void cp_async16(uint32_t saddr, const void* gaddr) {
    asm volatile("cp.async.ca.shared.global [%0], [%1], 16;\n"
                 :: "r"(saddr), "l"(gaddr));
}
#define CP_COMMIT() asm volatile("cp.async.commit_group;\n" ::: "memory")
#define CP_WAIT0()  asm volatile("cp.async.wait_group 0;\n" ::: "memory")

// ---------------------------------------------------------------------------
// Fused 4-bit dequant + HMMA GEMM:  C[M,N] = X[M,K] * dequant(Q)[K,N] + bias
//
// qweight: [K/8, N] int32, nibbles pack K (8 consecutive k per word)
// qzeros : [G, N/8] int32, nibbles pack N
// scales : [G, N] f32 (fp16 values)
//
// Dequant via fp16 magic numbers: fp16(0x6400|q) = 1024+q exactly, so
// (u - (1024+z)) * s == fp16(scale) * fp16(q - z) bit-exactly.
//
// B-tile dequant mapping: thread -> 4 consecutive N cols x 1 kp row, twice.
//   One LDG.128 of qweight per unit, STS.64 stores.
// Pipelining: stage ks computes A[ks&1],B[ks&1]; at stage start we STORE
//   B[nxt] from registers prefetched in stage ks-1 (buffer freed by the
//   barrier that ended ks-1), so the MMA chain is never trailed by dequant.
// ---------------------------------------------------------------------------
__global__ void __launch_bounds__(256)
gemm_q4_kernel(const int* __restrict__ qweight,
               const int* __restrict__ qzeros,
               const float* __restrict__ scales,
               const float* __restrict__ bias,
               float* __restrict__ out)
{
    extern __shared__ __align__(16) char smem[];
    const uint32_t sbase = smem_u32(smem);

    const int tid  = threadIdx.x;
    const int warp = tid >> 5;
    const int lane = tid & 31;
    const int bm   = blockIdx.x * BM;   // M fastest: A + qweight stay L2-resident
    const int bn   = blockIdx.y * BN;

    // warp tile: 64x64.  warp grid 2(M) x 4(N)
    const int wm = (warp >> 2) * 64;
    const int wn = (warp & 3) * 64;

    const __half* Xb = g_Xh + (size_t)bm * K_IN;

    // ---- B dequant mapping: 2 units of (1 kp row x 4 cols) per thread ----
    const int n0  = (tid & 63) * 4;          // 0,4,...,252
    const int kp0 = tid >> 6;                // 0..3 ; unit r adds 4*r
    const int o   = bn + n0;

    wmma::fragment<wmma::accumulator, 16, 16, 16, float> acc[4][4];
    #pragma unroll
    for (int i = 0; i < 4; i++)
        #pragma unroll
        for (int j = 0; j < 4; j++)
            wmma::fill_fragment(acc[i][j], 0.0f);

    uint4   breg[2];          // qweight words: 2 units x 4 cols
    __half2 hz01, hz23;       // (1024+z) pairs for cols 0,1 / 2,3
    __half2 hs01, hs23;       // scale pairs

    auto ldg_b = [&](int ks) {
        const int4* qw = (const int4*)(qweight + (size_t)(ks * 8 + kp0) * N_OUT + o);
        breg[0] = *(const uint4*)qw;
        breg[1] = *(const uint4*)((const int*)qw + 4 * (size_t)N_OUT);
    };
    auto ldg_consts = [&](int g) {
        uint32_t zw = (uint32_t)qzeros[(size_t)g * (N_OUT / 8) + (o >> 3)];
        uint32_t sh = (o & 7) * 4;      // 0 or 16
        uint32_t z0 = ((zw >> (sh + 0)) & 15u) + 1u + 0x6400u;
        uint32_t z1 = ((zw >> (sh + 4)) & 15u) + 1u + 0x6400u;
        uint32_t z2 = ((zw >> (sh + 8)) & 15u) + 1u + 0x6400u;
        uint32_t z3 = ((zw >> (sh + 12)) & 15u) + 1u + 0x6400u;
        uint32_t p01 = z0 | (z1 << 16), p23 = z2 | (z3 << 16);
        hz01 = *(__half2*)&p01;
        hz23 = *(__half2*)&p23;
        float4 s4 = *(const float4*)(scales + (size_t)g * N_OUT + o);
        hs01 = __halves2half2(__float2half_rn(s4.x), __float2half_rn(s4.y));
        hs23 = __halves2half2(__float2half_rn(s4.z), __float2half_rn(s4.w));
    };
    auto issue_a = [&](int ks, uint32_t abase) {
        const int k0 = ks * BK;
        #pragma unroll
        for (int i = 0; i < 4; i++) {
            int c = tid + 256 * i;
            int row = c >> 3, cc = c & 7;
            cp_async16(abase + (uint32_t)(row * A_LD + cc * 8) * 2,
                       Xb + (size_t)row * K_IN + k0 + cc * 8);
        }
    };
    auto store_b = [&](uint32_t bbyte) {
        #pragma unroll
        for (int r = 0; r < 2; r++) {
            uint4 w = breg[r];
            char* dst = smem + bbyte + ((kp0 + 4 * r) * 8) * (B_LD * 2) + n0 * 2;
            #pragma unroll
            for (int j = 0; j < 8; j++) {
                uint32_t u01 = 0x64006400u | ((w.x >> (4 * j)) & 0xFu)
                                           | (((w.y >> (4 * j)) & 0xFu) << 16);
                uint32_t u23 = 0x64006400u | ((w.z >> (4 * j)) & 0xFu)
                                           | (((w.w >> (4 * j)) & 0xFu) << 16);
                __half2 h01 = __hmul2(__hsub2(*(__half2*)&u01, hz01), hs01);
                __half2 h23 = __hmul2(__hsub2(*(__half2*)&u23, hz23), hs23);
                uint2 v = make_uint2(*(uint32_t*)&h01, *(uint32_t*)&h23);
                *(uint2*)(dst + j * (B_LD * 2)) = v;
            }
        }
    };

    // ---- prologue ----
    ldg_b(0);
    ldg_consts(0);                 // group of stage 0
    store_b(SMEM_B0);
    ldg_b(1);                      // stage 1 data; group(1)=0 -> consts ok
    issue_a(0, sbase + SMEM_A0);
    CP_COMMIT();
    CP_WAIT0();
    __syncthreads();

    const uint32_t a_off[2] = {SMEM_A0, SMEM_A1};
    const uint32_t b_off[2] = {SMEM_B0, SMEM_B1};

    for (int ks = 0; ks < NITER; ks++) {
        const int buf = ks & 1;
        const int nxt = buf ^ 1;

        if (ks + 1 < NITER) {
            issue_a(ks + 1, sbase + a_off[nxt]);
            CP_COMMIT();
            store_b(b_off[nxt]);               // B data for stage ks+1 (regs)
        }
        if (ks + 2 < NITER) {
            // consts for stage ks+2's group (changes when ks is even)
            if ((ks & 1) == 0)
                ldg_consts((ks + 2) >> 1);
            ldg_b(ks + 2);
        }

        // ---- compute on current buffers ----
        const __half* As = (const __half*)(smem + a_off[buf]);
        const __half* Bs = (const __half*)(smem + b_off[buf]);
        #pragma unroll
        for (int kk = 0; kk < BK; kk += 16) {
            wmma::fragment<wmma::matrix_a, 16, 16, 16, __half, wmma::row_major> af[4];
            #pragma unroll
            for (int i = 0; i < 4; i++)
                wmma::load_matrix_sync(af[i], As + (wm + i * 16) * A_LD + kk, A_LD);
            #pragma unroll
            for (int j = 0; j < 4; j++) {
                wmma::fragment<wmma::matrix_b, 16, 16, 16, __half, wmma::row_major> bf;
                wmma::load_matrix_sync(bf, Bs + kk * B_LD + wn + j * 16, B_LD);
                #pragma unroll
                for (int i = 0; i < 4; i++)
                    wmma::mma_sync(acc[i][j], af[i], bf, acc[i][j]);
            }
        }

        CP_WAIT0();
        __syncthreads();
    }

    // ---- epilogue: stage fp32 per warp (16x64 chunks), add bias, write ----
    float* fbuf = (float*)smem + warp * 16 * C_LD;
    const float* brow = bias + bn + wn;
    #pragma unroll
    for (int i = 0; i < 4; i++) {
        #pragma unroll
        for (int j = 0; j < 4; j++)
            wmma::store_matrix_sync(fbuf + j * 16, acc[i][j], C_LD, wmma::mem_row_major);
        __syncwarp();
        #pragma unroll
        for (int ii = 0; ii < 8; ii++) {
            int idx4 = lane + 32 * ii;          // 256 float4 = 16x64
            int row  = idx4 >> 4;
            int col  = (idx4 & 15) * 4;
            float4 v = *(float4*)(fbuf + row * C_LD + col);
            float4 b4 = *(const float4*)(brow + col);
            v.x += b4.x; v.y += b4.y; v.z += b4.z; v.w += b4.w;
            *(float4*)(out + (size_t)(bm + wm + i * 16 + row) * N_OUT + bn + wn + col) = v;
        }
        __syncwarp();
    }
}

// ---------------------------------------------------------------------------
// Launch.  Inputs: x(f32), qweight(i32), qzeros(i32), scales(f32), g_idx(i32),
//                  bias(f32).  Output f32 [M_TOK, N_OUT].
// ---------------------------------------------------------------------------
extern "C" void kernel_launch(void* const* d_in, const int* in_sizes, int n_in,
                              void* d_out, int out_size)
{
    const float* x       = (const float*)d_in[0];
    const int*   qweight = (const int*)d_in[1];
    const int*   qzeros  = (const int*)d_in[2];
    const float* scales  = (const float*)d_in[3];
    const float* bias    = (const float*)d_in[5];
    float* out = (float*)d_out;

    {
        size_t n4 = (size_t)M_TOK * K_IN / 4;
        convert_x_kernel<<<(unsigned)((n4 + 255) / 256), 256>>>(x);
    }
    {
        cudaFuncSetAttribute(gemm_q4_kernel,
                             cudaFuncAttributeMaxDynamicSharedMemorySize,
                             SMEM_DYN);
        dim3 grid(M_TOK / BM, N_OUT / BN);   // (32, 43), M fastest
        gemm_q4_kernel<<<grid, 256, SMEM_DYN>>>(qweight, qzeros, scales, bias, out);
    }
}

// round 7
// speedup vs baseline: 2.2578x; 1.0602x over previous
#include <cuda_runtime.h>
#include <cuda_fp16.h>
#include <mma.h>
#include <cstdint>

using namespace nvcuda;

// ---------------------------------------------------------------------------
// Problem constants
// ---------------------------------------------------------------------------
#define M_TOK   4096
#define K_IN    4096
#define N_OUT   11008
#define GROUPSZ 128

// GEMM tiling
#define BM      128
#define BN      256
#define BK      64
#define NITER   (K_IN / BK)        // 64
#define NTHREADS 512               // 16 warps, warp tile 32x64 (grid 4M x 4N)

#define A_LD    72                 // 64 + 8 pad (halves)
#define B_LD    264                // 256 + 8 pad (halves)
#define C_LD    68                 // 64 + 4 pad (floats), epilogue staging

#define A_STAGE_BYTES (BM * A_LD * 2)      // 18432
#define B_STAGE_BYTES (BK * B_LD * 2)      // 33792
#define SMEM_A0  0
#define SMEM_A1  (A_STAGE_BYTES)
#define SMEM_B0  (2 * A_STAGE_BYTES)
#define SMEM_B1  (2 * A_STAGE_BYTES + B_STAGE_BYTES)
#define SMEM_DYN (2 * A_STAGE_BYTES + 2 * B_STAGE_BYTES)   // 104448

// fp16 x scratch (no allocations allowed)
__device__ __half g_Xh[(size_t)M_TOK * K_IN];

// ---------------------------------------------------------------------------
// Kernel 0: convert x f32 -> f16 (harness materializes jax f16 as f32)
// ---------------------------------------------------------------------------
__global__ void convert_x_kernel(const float* __restrict__ x)
{
    size_t i = ((size_t)blockIdx.x * blockDim.x + threadIdx.x) * 4;
    if (i >= (size_t)M_TOK * K_IN) return;
    float4 v = *(const float4*)(x + i);
    *(__half2*)(g_Xh + i)     = __floats2half2_rn(v.x, v.y);
    *(__half2*)(g_Xh + i + 2) = __floats2half2_rn(v.z, v.w);
}

// ---------------------------------------------------------------------------
// helpers
// ---------------------------------------------------------------------------
__device__ __forceinline__ uint32_t smem_u32(const void* p) {
    uint32_t a;
    asm("{ .reg .u64 t; cvta.to.shared.u64 t, %1; cvt.u32.u64 %0, t; }"
        : "=r"(a) : "l"(p));
    return a;
}
__device__ __forceinline__ void cp_async16(uint32_t saddr, const void* gaddr) {
    asm volatile("cp.async.ca.shared.global [%0], [%1], 16;\n"
                 :: "r"(saddr), "l"(gaddr));
}
#define CP_COMMIT() asm volatile("cp.async.commit_group;\n" ::: "memory")
#define CP_WAIT0()  asm volatile("cp.async.wait_group 0;\n" ::: "memory")

// ---------------------------------------------------------------------------
// Fused 4-bit dequant + HMMA GEMM:  C[M,N] = X[M,K] * dequant(Q)[K,N] + bias
//
// qweight: [K/8, N] int32, nibbles pack K (8 consecutive k per word)
// qzeros : [G, N/8] int32, nibbles pack N
// scales : [G, N] f32 (fp16 values)
//
// Dequant via fp16 magic numbers: fp16(0x6400|q) = 1024+q exactly, so
// (u - (1024+z)) * s == fp16(scale) * fp16(q - z) bit-exactly.
//
// 512 threads: B dequant = 1 LDG.128 (kp row kp0, 4 cols) + 8 STS.64 per
// stage per thread; A = 2 cp.async per stage per thread.
// Pipelining: stage ks computes buffers[ks&1]; at stage start we store
// B[nxt] from regs prefetched in stage ks-1, then prefetch ks+2's regs.
// ---------------------------------------------------------------------------
__global__ void __launch_bounds__(NTHREADS, 1)
gemm_q4_kernel(const int* __restrict__ qweight,
               const int* __restrict__ qzeros,
               const float* __restrict__ scales,
               const float* __restrict__ bias,
               float* __restrict__ out)
{
    extern __shared__ __align__(16) char smem[];
    const uint32_t sbase = smem_u32(smem);

    const int tid  = threadIdx.x;
    const int warp = tid >> 5;
    const int lane = tid & 31;
    const int bm   = blockIdx.x * BM;   // M fastest: A + qweight stay L2-resident
    const int bn   = blockIdx.y * BN;

    // warp tile: 32x64.  warp grid 4(M) x 4(N)
    const int wm = (warp >> 2) * 32;
    const int wn = (warp & 3) * 64;

    const __half* Xb = g_Xh + (size_t)bm * K_IN;

    // ---- B dequant mapping: 1 unit of (1 kp row x 4 cols) per thread ----
    const int n0  = (tid & 63) * 4;          // 0,4,...,252
    const int kp0 = tid >> 6;                // 0..7
    const int o   = bn + n0;

    wmma::fragment<wmma::accumulator, 16, 16, 16, float> acc[2][4];
    #pragma unroll
    for (int i = 0; i < 2; i++)
        #pragma unroll
        for (int j = 0; j < 4; j++)
            wmma::fill_fragment(acc[i][j], 0.0f);

    uint4   breg;             // qweight words: 4 cols of one kp row
    __half2 hz01, hz23;       // (1024+z) pairs for cols 0,1 / 2,3
    __half2 hs01, hs23;       // scale pairs

    auto ldg_b = [&](int ks) {
        breg = *(const uint4*)(qweight + (size_t)(ks * 8 + kp0) * N_OUT + o);
    };
    auto ldg_consts = [&](int g) {
        uint32_t zw = (uint32_t)qzeros[(size_t)g * (N_OUT / 8) + (o >> 3)];
        uint32_t sh = (o & 7) * 4;      // 0 or 16
        uint32_t z0 = ((zw >> (sh + 0)) & 15u) + 1u + 0x6400u;
        uint32_t z1 = ((zw >> (sh + 4)) & 15u) + 1u + 0x6400u;
        uint32_t z2 = ((zw >> (sh + 8)) & 15u) + 1u + 0x6400u;
        uint32_t z3 = ((zw >> (sh + 12)) & 15u) + 1u + 0x6400u;
        uint32_t p01 = z0 | (z1 << 16), p23 = z2 | (z3 << 16);
        hz01 = *(__half2*)&p01;
        hz23 = *(__half2*)&p23;
        float4 s4 = *(const float4*)(scales + (size_t)g * N_OUT + o);
        hs01 = __halves2half2(__float2half_rn(s4.x), __float2half_rn(s4.y));
        hs23 = __halves2half2(__float2half_rn(s4.z), __float2half_rn(s4.w));
    };
    auto issue_a = [&](int ks, uint32_t abase) {
        const int k0 = ks * BK;
        #pragma unroll
        for (int i = 0; i < 2; i++) {
            int c = tid + NTHREADS * i;
            int row = c >> 3, cc = c & 7;
            cp_async16(abase + (uint32_t)(row * A_LD + cc * 8) * 2,
                       Xb + (size_t)row * K_IN + k0 + cc * 8);
        }
    };
    auto store_b = [&](uint32_t bbyte) {
        char* dst = smem + bbyte + (kp0 * 8) * (B_LD * 2) + n0 * 2;
        uint4 w = breg;
        #pragma unroll
        for (int j = 0; j < 8; j++) {
            uint32_t u01 = 0x64006400u | ((w.x >> (4 * j)) & 0xFu)
                                       | (((w.y >> (4 * j)) & 0xFu) << 16);
            uint32_t u23 = 0x64006400u | ((w.z >> (4 * j)) & 0xFu)
                                       | (((w.w >> (4 * j)) & 0xFu) << 16);
            __half2 h01 = __hmul2(__hsub2(*(__half2*)&u01, hz01), hs01);
            __half2 h23 = __hmul2(__hsub2(*(__half2*)&u23, hz23), hs23);
            uint2 v = make_uint2(*(uint32_t*)&h01, *(uint32_t*)&h23);
            *(uint2*)(dst + j * (B_LD * 2)) = v;
        }
    };

    // ---- prologue ----
    ldg_b(0);
    ldg_consts(0);                 // group of stages 0,1
    store_b(SMEM_B0);
    ldg_b(1);
    issue_a(0, sbase + SMEM_A0);
    CP_COMMIT();
    CP_WAIT0();
    __syncthreads();

    const uint32_t a_off[2] = {SMEM_A0, SMEM_A1};
    const uint32_t b_off[2] = {SMEM_B0, SMEM_B1};

    for (int ks = 0; ks < NITER; ks++) {
        const int buf = ks & 1;
        const int nxt = buf ^ 1;

        if (ks + 1 < NITER) {
            issue_a(ks + 1, sbase + a_off[nxt]);
            CP_COMMIT();
            store_b(b_off[nxt]);               // B data for stage ks+1 (regs)
        }
        if (ks + 2 < NITER) {
            if ((ks & 1) == 0)
                ldg_consts((ks + 2) >> 1);     // group for stages ks+2, ks+3
            ldg_b(ks + 2);
        }

        // ---- compute on current buffers ----
        const __half* As = (const __half*)(smem + a_off[buf]);
        const __half* Bs = (const __half*)(smem + b_off[buf]);
        #pragma unroll
        for (int kk = 0; kk < BK; kk += 16) {
            wmma::fragment<wmma::matrix_a, 16, 16, 16, __half, wmma::row_major> af[2];
            #pragma unroll
            for (int i = 0; i < 2; i++)
                wmma::load_matrix_sync(af[i], As + (wm + i * 16) * A_LD + kk, A_LD);
            #pragma unroll
            for (int j = 0; j < 4; j++) {
                wmma::fragment<wmma::matrix_b, 16, 16, 16, __half, wmma::row_major> bf;
                wmma::load_matrix_sync(bf, Bs + kk * B_LD + wn + j * 16, B_LD);
                #pragma unroll
                for (int i = 0; i < 2; i++)
                    wmma::mma_sync(acc[i][j], af[i], bf, acc[i][j]);
            }
        }

        CP_WAIT0();
        __syncthreads();
    }

    // ---- epilogue: stage fp32 per warp (16x64 chunks), add bias, write ----
    float* fbuf = (float*)smem + warp * 16 * C_LD;
    const float* brow = bias + bn + wn;
    #pragma unroll
    for (int i = 0; i < 2; i++) {
        #pragma unroll
        for (int j = 0; j < 4; j++)
            wmma::store_matrix_sync(fbuf + j * 16, acc[i][j], C_LD, wmma::mem_row_major);
        __syncwarp();
        #pragma unroll
        for (int ii = 0; ii < 8; ii++) {
            int idx4 = lane + 32 * ii;          // 256 float4 = 16x64
            int row  = idx4 >> 4;
            int col  = (idx4 & 15) * 4;
            float4 v = *(float4*)(fbuf + row * C_LD + col);
            float4 b4 = *(const float4*)(brow + col);
            v.x += b4.x; v.y += b4.y; v.z += b4.z; v.w += b4.w;
            *(float4*)(out + (size_t)(bm + wm + i * 16 + row) * N_OUT + bn + wn + col) = v;
        }
        __syncwarp();
    }
}

// ---------------------------------------------------------------------------
// Launch.  Inputs: x(f32), qweight(i32), qzeros(i32), scales(f32), g_idx(i32),
//                  bias(f32).  Output f32 [M_TOK, N_OUT].
// ---------------------------------------------------------------------------
extern "C" void kernel_launch(void* const* d_in, const int* in_sizes, int n_in,
                              void* d_out, int out_size)
{
    const float* x       = (const float*)d_in[0];
    const int*   qweight = (const int*)d_in[1];
    const int*   qzeros  = (const int*)d_in[2];
    const float* scales  = (const float*)d_in[3];
    const float* bias    = (const float*)d_in[5];
    float* out = (float*)d_out;

    {
        size_t n4 = (size_t)M_TOK * K_IN / 4;
        convert_x_kernel<<<(unsigned)((n4 + 255) / 256), 256>>>(x);
    }
    {
        cudaFuncSetAttribute(gemm_q4_kernel,
                             cudaFuncAttributeMaxDynamicSharedMemorySize,
                             SMEM_DYN);
        dim3 grid(M_TOK / BM, N_OUT / BN);   // (32, 43), M fastest
        gemm_q4_kernel<<<grid, NTHREADS, SMEM_DYN>>>(qweight, qzeros, scales, bias, out);
    }
}

// round 8
// speedup vs baseline: 2.4936x; 1.1045x over previous
#include <cuda_runtime.h>
#include <cuda_fp16.h>
#include <mma.h>
#include <cstdint>

using namespace nvcuda;

// ---------------------------------------------------------------------------
// Problem constants
// ---------------------------------------------------------------------------
#define M_TOK   4096
#define K_IN    4096
#define N_OUT   11008
#define GROUPSZ 128

// GEMM tiling: 2 CTAs/SM for barrier overlap
#define BM      128
#define BN      128
#define BK      64
#define NITER   (K_IN / BK)        // 64
#define NTHREADS 256               // 8 warps, warp tile 32x64 (grid 4M x 2N)

#define A_LD    72                 // 64 + 8 pad (halves)
#define B_LD    136                // 128 + 8 pad (halves)
#define C_LD    68                 // 64 + 4 pad (floats), epilogue staging

#define A_STAGE_BYTES (BM * A_LD * 2)      // 18432
#define B_STAGE_BYTES (BK * B_LD * 2)      // 17408
#define SMEM_A0  0
#define SMEM_A1  (A_STAGE_BYTES)
#define SMEM_B0  (2 * A_STAGE_BYTES)
#define SMEM_B1  (2 * A_STAGE_BYTES + B_STAGE_BYTES)
#define SMEM_DYN (2 * A_STAGE_BYTES + 2 * B_STAGE_BYTES)   // 71680

// fp16 x scratch (no allocations allowed)
__device__ __half g_Xh[(size_t)M_TOK * K_IN];

// ---------------------------------------------------------------------------
// Kernel 0: convert x f32 -> f16 (harness materializes jax f16 as f32)
// ---------------------------------------------------------------------------
__global__ void convert_x_kernel(const float* __restrict__ x)
{
    size_t i = ((size_t)blockIdx.x * blockDim.x + threadIdx.x) * 4;
    if (i >= (size_t)M_TOK * K_IN) return;
    float4 v = *(const float4*)(x + i);
    *(__half2*)(g_Xh + i)     = __floats2half2_rn(v.x, v.y);
    *(__half2*)(g_Xh + i + 2) = __floats2half2_rn(v.z, v.w);
}

// ---------------------------------------------------------------------------
// helpers
// ---------------------------------------------------------------------------
__device__ __forceinline__ uint32_t smem_u32(const void* p) {
    uint32_t a;
    asm("{ .reg .u64 t; cvta.to.shared.u64 t, %1; cvt.u32.u64 %0, t; }"
        : "=r"(a) : "l"(p));
    return a;
}
__device__ __forceinline__ void cp_async16(uint32_t saddr, const void* gaddr) {
    asm volatile("cp.async.ca.shared.global [%0], [%1], 16;\n"
                 :: "r"(saddr), "l"(gaddr));
}
#define CP_COMMIT() asm volatile("cp.async.commit_group;\n" ::: "memory")
#define CP_WAIT0()  asm volatile("cp.async.wait_group 0;\n" ::: "memory")

// ---------------------------------------------------------------------------
// Fused 4-bit dequant + HMMA GEMM:  C[M,N] = X[M,K] * dequant(Q)[K,N] + bias
//
// qweight: [K/8, N] int32, nibbles pack K (8 consecutive k per word)
// qzeros : [G, N/8] int32, nibbles pack N
// scales : [G, N] f32 (fp16 values)
//
// Dequant via fp16 magic numbers: fp16(0x6400|q) = 1024+q exactly, so
// (u - (1024+z)) * s == fp16(scale) * fp16(q - z) bit-exactly.
//
// 256 threads, 2 CTAs/SM: barrier phases of the two CTAs are independent,
// so one CTA's warps issue HMMAs while the other waits at its barrier.
// B dequant = 1 LDG.128 (kp row kp0, 4 cols) + 8 STS.64 per stage/thread;
// A = 4 cp.async per stage/thread. Stage ks computes buffers[ks&1]; at
// stage start we store B[nxt] from regs prefetched in ks-1, then prefetch
// ks+2's regs.
// ---------------------------------------------------------------------------
__global__ void __launch_bounds__(NTHREADS, 2)
gemm_q4_kernel(const int* __restrict__ qweight,
               const int* __restrict__ qzeros,
               const float* __restrict__ scales,
               const float* __restrict__ bias,
               float* __restrict__ out)
{
    extern __shared__ __align__(16) char smem[];
    const uint32_t sbase = smem_u32(smem);

    const int tid  = threadIdx.x;
    const int warp = tid >> 5;
    const int lane = tid & 31;
    const int bm   = blockIdx.x * BM;   // M fastest: A + qweight stay L2-resident
    const int bn   = blockIdx.y * BN;

    // warp tile: 32x64.  warp grid 4(M) x 2(N)
    const int wm = (warp >> 1) * 32;
    const int wn = (warp & 1) * 64;

    const __half* Xb = g_Xh + (size_t)bm * K_IN;

    // ---- B dequant mapping: 1 unit of (1 kp row x 4 cols) per thread ----
    const int n0  = (tid & 31) * 4;          // 0,4,...,124
    const int kp0 = tid >> 5;                // 0..7
    const int o   = bn + n0;

    wmma::fragment<wmma::accumulator, 16, 16, 16, float> acc[2][4];
    #pragma unroll
    for (int i = 0; i < 2; i++)
        #pragma unroll
        for (int j = 0; j < 4; j++)
            wmma::fill_fragment(acc[i][j], 0.0f);

    uint4   breg;             // qweight words: 4 cols of one kp row
    __half2 hz01, hz23;       // (1024+z) pairs for cols 0,1 / 2,3
    __half2 hs01, hs23;       // scale pairs

    auto ldg_b = [&](int ks) {
        breg = *(const uint4*)(qweight + (size_t)(ks * 8 + kp0) * N_OUT + o);
    };
    auto ldg_consts = [&](int g) {
        uint32_t zw = (uint32_t)qzeros[(size_t)g * (N_OUT / 8) + (o >> 3)];
        uint32_t sh = (o & 7) * 4;      // 0 or 16
        uint32_t z0 = ((zw >> (sh + 0)) & 15u) + 1u + 0x6400u;
        uint32_t z1 = ((zw >> (sh + 4)) & 15u) + 1u + 0x6400u;
        uint32_t z2 = ((zw >> (sh + 8)) & 15u) + 1u + 0x6400u;
        uint32_t z3 = ((zw >> (sh + 12)) & 15u) + 1u + 0x6400u;
        uint32_t p01 = z0 | (z1 << 16), p23 = z2 | (z3 << 16);
        hz01 = *(__half2*)&p01;
        hz23 = *(__half2*)&p23;
        float4 s4 = *(const float4*)(scales + (size_t)g * N_OUT + o);
        hs01 = __halves2half2(__float2half_rn(s4.x), __float2half_rn(s4.y));
        hs23 = __halves2half2(__float2half_rn(s4.z), __float2half_rn(s4.w));
    };
    auto issue_a = [&](int ks, uint32_t abase) {
        const int k0 = ks * BK;
        #pragma unroll
        for (int i = 0; i < 4; i++) {
            int c = tid + NTHREADS * i;
            int row = c >> 3, cc = c & 7;
            cp_async16(abase + (uint32_t)(row * A_LD + cc * 8) * 2,
                       Xb + (size_t)row * K_IN + k0 + cc * 8);
        }
    };
    auto store_b = [&](uint32_t bbyte) {
        char* dst = smem + bbyte + (kp0 * 8) * (B_LD * 2) + n0 * 2;
        uint4 w = breg;
        #pragma unroll
        for (int j = 0; j < 8; j++) {
            uint32_t u01 = 0x64006400u | ((w.x >> (4 * j)) & 0xFu)
                                       | (((w.y >> (4 * j)) & 0xFu) << 16);
            uint32_t u23 = 0x64006400u | ((w.z >> (4 * j)) & 0xFu)
                                       | (((w.w >> (4 * j)) & 0xFu) << 16);
            __half2 h01 = __hmul2(__hsub2(*(__half2*)&u01, hz01), hs01);
            __half2 h23 = __hmul2(__hsub2(*(__half2*)&u23, hz23), hs23);
            uint2 v = make_uint2(*(uint32_t*)&h01, *(uint32_t*)&h23);
            *(uint2*)(dst + j * (B_LD * 2)) = v;
        }
    };

    // ---- prologue ----
    ldg_b(0);
    ldg_consts(0);                 // group of stages 0,1
    store_b(SMEM_B0);
    ldg_b(1);
    issue_a(0, sbase + SMEM_A0);
    CP_COMMIT();
    CP_WAIT0();
    __syncthreads();

    const uint32_t a_off[2] = {SMEM_A0, SMEM_A1};
    const uint32_t b_off[2] = {SMEM_B0, SMEM_B1};

    for (int ks = 0; ks < NITER; ks++) {
        const int buf = ks & 1;
        const int nxt = buf ^ 1;

        if (ks + 1 < NITER) {
            issue_a(ks + 1, sbase + a_off[nxt]);
            CP_COMMIT();
            store_b(b_off[nxt]);               // B data for stage ks+1 (regs)
        }
        if (ks + 2 < NITER) {
            if ((ks & 1) == 0)
                ldg_consts((ks + 2) >> 1);     // group for stages ks+2, ks+3
            ldg_b(ks + 2);
        }

        // ---- compute on current buffers ----
        const __half* As = (const __half*)(smem + a_off[buf]);
        const __half* Bs = (const __half*)(smem + b_off[buf]);
        #pragma unroll
        for (int kk = 0; kk < BK; kk += 16) {
            wmma::fragment<wmma::matrix_a, 16, 16, 16, __half, wmma::row_major> af[2];
            #pragma unroll
            for (int i = 0; i < 2; i++)
                wmma::load_matrix_sync(af[i], As + (wm + i * 16) * A_LD + kk, A_LD);
            #pragma unroll
            for (int j = 0; j < 4; j++) {
                wmma::fragment<wmma::matrix_b, 16, 16, 16, __half, wmma::row_major> bf;
                wmma::load_matrix_sync(bf, Bs + kk * B_LD + wn + j * 16, B_LD);
                #pragma unroll
                for (int i = 0; i < 2; i++)
                    wmma::mma_sync(acc[i][j], af[i], bf, acc[i][j]);
            }
        }

        CP_WAIT0();
        __syncthreads();
    }

    // ---- epilogue: stage fp32 per warp (16x64 chunks), add bias, write ----
    float* fbuf = (float*)smem + warp * 16 * C_LD;
    const float* brow = bias + bn + wn;
    #pragma unroll
    for (int i = 0; i < 2; i++) {
        #pragma unroll
        for (int j = 0; j < 4; j++)
            wmma::store_matrix_sync(fbuf + j * 16, acc[i][j], C_LD, wmma::mem_row_major);
        __syncwarp();
        #pragma unroll
        for (int ii = 0; ii < 8; ii++) {
            int idx4 = lane + 32 * ii;          // 256 float4 = 16x64
            int row  = idx4 >> 4;
            int col  = (idx4 & 15) * 4;
            float4 v = *(float4*)(fbuf + row * C_LD + col);
            float4 b4 = *(const float4*)(brow + col);
            v.x += b4.x; v.y += b4.y; v.z += b4.z; v.w += b4.w;
            *(float4*)(out + (size_t)(bm + wm + i * 16 + row) * N_OUT + bn + wn + col) = v;
        }
        __syncwarp();
    }
}

// ---------------------------------------------------------------------------
// Launch.  Inputs: x(f32), qweight(i32), qzeros(i32), scales(f32), g_idx(i32),
//                  bias(f32).  Output f32 [M_TOK, N_OUT].
// ---------------------------------------------------------------------------
extern "C" void kernel_launch(void* const* d_in, const int* in_sizes, int n_in,
                              void* d_out, int out_size)
{
    const float* x       = (const float*)d_in[0];
    const int*   qweight = (const int*)d_in[1];
    const int*   qzeros  = (const int*)d_in[2];
    const float* scales  = (const float*)d_in[3];
    const float* bias    = (const float*)d_in[5];
    float* out = (float*)d_out;

    {
        size_t n4 = (size_t)M_TOK * K_IN / 4;
        convert_x_kernel<<<(unsigned)((n4 + 255) / 256), 256>>>(x);
    }
    {
        cudaFuncSetAttribute(gemm_q4_kernel,
                             cudaFuncAttributeMaxDynamicSharedMemorySize,
                             SMEM_DYN);
        dim3 grid(M_TOK / BM, N_OUT / BN);   // (32, 86), M fastest
        gemm_q4_kernel<<<grid, NTHREADS, SMEM_DYN>>>(qweight, qzeros, scales, bias, out);
    }
}

// round 9
// speedup vs baseline: 2.6583x; 1.0661x over previous
#include <cuda_runtime.h>
#include <cuda_fp16.h>
#include <mma.h>
#include <cstdint>

using namespace nvcuda;

// ---------------------------------------------------------------------------
// Problem constants
// ---------------------------------------------------------------------------
#define M_TOK   4096
#define K_IN    4096
#define N_OUT   11008
#define GROUPSZ 128

// GEMM tiling: 4 warps, warp tile 64x64, 2 CTAs/SM
#define BM      128
#define BN      128
#define BK      64
#define NITER   (K_IN / BK)        // 64
#define NTHREADS 128               // 4 warps, warp grid 2(M) x 2(N)

#define A_LD    72                 // 64 + 8 pad (halves)
#define B_LD    136                // 128 + 8 pad (halves)
#define C_LD    68                 // 64 + 4 pad (floats), epilogue staging

#define A_STAGE_BYTES (BM * A_LD * 2)      // 18432
#define B_STAGE_BYTES (BK * B_LD * 2)      // 17408
#define SMEM_A0  0
#define SMEM_A1  (A_STAGE_BYTES)
#define SMEM_B0  (2 * A_STAGE_BYTES)
#define SMEM_B1  (2 * A_STAGE_BYTES + B_STAGE_BYTES)
#define SMEM_DYN (2 * A_STAGE_BYTES + 2 * B_STAGE_BYTES)   // 71680

// fp16 x scratch (no allocations allowed)
__device__ __half g_Xh[(size_t)M_TOK * K_IN];

// ---------------------------------------------------------------------------
// Kernel 0: convert x f32 -> f16 (harness materializes jax f16 as f32)
// ---------------------------------------------------------------------------
__global__ void convert_x_kernel(const float* __restrict__ x)
{
    size_t i = ((size_t)blockIdx.x * blockDim.x + threadIdx.x) * 4;
    if (i >= (size_t)M_TOK * K_IN) return;
    float4 v = *(const float4*)(x + i);
    *(__half2*)(g_Xh + i)     = __floats2half2_rn(v.x, v.y);
    *(__half2*)(g_Xh + i + 2) = __floats2half2_rn(v.z, v.w);
}

// ---------------------------------------------------------------------------
// helpers
// ---------------------------------------------------------------------------
__device__ __forceinline__ uint32_t smem_u32(const void* p) {
    uint32_t a;
    asm("{ .reg .u64 t; cvta.to.shared.u64 t, %1; cvt.u32.u64 %0, t; }"
        : "=r"(a) : "l"(p));
    return a;
}
__device__ __forceinline__ void cp_async16(uint32_t saddr, const void* gaddr) {
    asm volatile("cp.async.ca.shared.global [%0], [%1], 16;\n"
                 :: "r"(saddr), "l"(gaddr));
}
#define CP_COMMIT() asm volatile("cp.async.commit_group;\n" ::: "memory")
#define CP_WAIT0()  asm volatile("cp.async.wait_group 0;\n" ::: "memory")

// ---------------------------------------------------------------------------
// Fused 4-bit dequant + HMMA GEMM:  C[M,N] = X[M,K] * dequant(Q)[K,N] + bias
//
// qweight: [K/8, N] int32, nibbles pack K (8 consecutive k per word)
// qzeros : [G, N/8] int32, nibbles pack N
// scales : [G, N] f32 (fp16 values)
//
// Dequant via fp16 magic numbers: fp16(0x6400|q) = 1024+q exactly, so
// (u - (1024+z)) * s == fp16(scale) * fp16(q - z) bit-exactly.
//
// 128 threads, 64x64 warp tiles: smem fragment re-reads drop to 2x per
// operand (vs 4x for B at 32x64), cutting L1/shared pressure 1.5x.
// 2 CTAs/SM overlap barrier phases.
// Per thread per stage: B = 2 LDG.128 (kp row kp0, 8 cols) + 8 STS.128;
// A = 8 cp.async. Stage ks computes buffers[ks&1]; at stage start we store
// B[nxt] from regs prefetched in ks-1, then prefetch ks+2's regs.
// ---------------------------------------------------------------------------
__global__ void __launch_bounds__(NTHREADS, 2)
gemm_q4_kernel(const int* __restrict__ qweight,
               const int* __restrict__ qzeros,
               const float* __restrict__ scales,
               const float* __restrict__ bias,
               float* __restrict__ out)
{
    extern __shared__ __align__(16) char smem[];
    const uint32_t sbase = smem_u32(smem);

    const int tid  = threadIdx.x;
    const int warp = tid >> 5;
    const int lane = tid & 31;
    const int bm   = blockIdx.x * BM;   // M fastest: A + qweight stay L2-resident
    const int bn   = blockIdx.y * BN;

    // warp tile: 64x64.  warp grid 2(M) x 2(N)
    const int wm = (warp >> 1) * 64;
    const int wn = (warp & 1) * 64;

    const __half* Xb = g_Xh + (size_t)bm * K_IN;

    // ---- B dequant mapping: 1 kp row x 8 cols per thread ----
    const int n0  = (tid & 15) * 8;          // 0,8,...,120
    const int kp0 = tid >> 4;                // 0..7
    const int o   = bn + n0;                 // multiple of 8: one qzeros word

    wmma::fragment<wmma::accumulator, 16, 16, 16, float> acc[4][4];
    #pragma unroll
    for (int i = 0; i < 4; i++)
        #pragma unroll
        for (int j = 0; j < 4; j++)
            wmma::fill_fragment(acc[i][j], 0.0f);

    uint4   breg[2];          // qweight words: 8 cols of one kp row
    __half2 hz[4];            // (1024+z) pairs for col pairs
    __half2 hs[4];            // scale pairs

    auto ldg_b = [&](int ks) {
        const int* qw = qweight + (size_t)(ks * 8 + kp0) * N_OUT + o;
        breg[0] = *(const uint4*)qw;
        breg[1] = *(const uint4*)(qw + 4);
    };
    auto ldg_consts = [&](int g) {
        uint32_t zw = (uint32_t)qzeros[(size_t)g * (N_OUT / 8) + (o >> 3)];
        #pragma unroll
        for (int k = 0; k < 4; k++) {
            uint32_t z0 = ((zw >> (8 * k))     & 15u) + 1u + 0x6400u;
            uint32_t z1 = ((zw >> (8 * k + 4)) & 15u) + 1u + 0x6400u;
            uint32_t p  = z0 | (z1 << 16);
            hz[k] = *(__half2*)&p;
        }
        float4 s0 = *(const float4*)(scales + (size_t)g * N_OUT + o);
        float4 s1 = *(const float4*)(scales + (size_t)g * N_OUT + o + 4);
        hs[0] = __halves2half2(__float2half_rn(s0.x), __float2half_rn(s0.y));
        hs[1] = __halves2half2(__float2half_rn(s0.z), __float2half_rn(s0.w));
        hs[2] = __halves2half2(__float2half_rn(s1.x), __float2half_rn(s1.y));
        hs[3] = __halves2half2(__float2half_rn(s1.z), __float2half_rn(s1.w));
    };
    auto issue_a = [&](int ks, uint32_t abase) {
        const int k0 = ks * BK;
        #pragma unroll
        for (int i = 0; i < 8; i++) {
            int c = tid + NTHREADS * i;
            int row = c >> 3, cc = c & 7;
            cp_async16(abase + (uint32_t)(row * A_LD + cc * 8) * 2,
                       Xb + (size_t)row * K_IN + k0 + cc * 8);
        }
    };
    auto store_b = [&](uint32_t bbyte) {
        char* dst = smem + bbyte + (kp0 * 8) * (B_LD * 2) + n0 * 2;
        uint4 wa = breg[0], wb = breg[1];
        #pragma unroll
        for (int j = 0; j < 8; j++) {
            uint32_t u01 = 0x64006400u | ((wa.x >> (4 * j)) & 0xFu)
                                       | (((wa.y >> (4 * j)) & 0xFu) << 16);
            uint32_t u23 = 0x64006400u | ((wa.z >> (4 * j)) & 0xFu)
                                       | (((wa.w >> (4 * j)) & 0xFu) << 16);
            uint32_t u45 = 0x64006400u | ((wb.x >> (4 * j)) & 0xFu)
                                       | (((wb.y >> (4 * j)) & 0xFu) << 16);
            uint32_t u67 = 0x64006400u | ((wb.z >> (4 * j)) & 0xFu)
                                       | (((wb.w >> (4 * j)) & 0xFu) << 16);
            __half2 h01 = __hmul2(__hsub2(*(__half2*)&u01, hz[0]), hs[0]);
            __half2 h23 = __hmul2(__hsub2(*(__half2*)&u23, hz[1]), hs[1]);
            __half2 h45 = __hmul2(__hsub2(*(__half2*)&u45, hz[2]), hs[2]);
            __half2 h67 = __hmul2(__hsub2(*(__half2*)&u67, hz[3]), hs[3]);
            uint4 v = make_uint4(*(uint32_t*)&h01, *(uint32_t*)&h23,
                                 *(uint32_t*)&h45, *(uint32_t*)&h67);
            *(uint4*)(dst + j * (B_LD * 2)) = v;
        }
    };

    // ---- prologue ----
    ldg_b(0);
    ldg_consts(0);                 // group of stages 0,1
    store_b(SMEM_B0);
    ldg_b(1);
    issue_a(0, sbase + SMEM_A0);
    CP_COMMIT();
    CP_WAIT0();
    __syncthreads();

    const uint32_t a_off[2] = {SMEM_A0, SMEM_A1};
    const uint32_t b_off[2] = {SMEM_B0, SMEM_B1};

    for (int ks = 0; ks < NITER; ks++) {
        const int buf = ks & 1;
        const int nxt = buf ^ 1;

        if (ks + 1 < NITER) {
            issue_a(ks + 1, sbase + a_off[nxt]);
            CP_COMMIT();
            store_b(b_off[nxt]);               // B data for stage ks+1 (regs)
        }
        if (ks + 2 < NITER) {
            if ((ks & 1) == 0)
                ldg_consts((ks + 2) >> 1);     // group for stages ks+2, ks+3
            ldg_b(ks + 2);
        }

        // ---- compute on current buffers ----
        const __half* As = (const __half*)(smem + a_off[buf]);
        const __half* Bs = (const __half*)(smem + b_off[buf]);
        #pragma unroll
        for (int kk = 0; kk < BK; kk += 16) {
            wmma::fragment<wmma::matrix_a, 16, 16, 16, __half, wmma::row_major> af[4];
            #pragma unroll
            for (int i = 0; i < 4; i++)
                wmma::load_matrix_sync(af[i], As + (wm + i * 16) * A_LD + kk, A_LD);
            #pragma unroll
            for (int j = 0; j < 4; j++) {
                wmma::fragment<wmma::matrix_b, 16, 16, 16, __half, wmma::row_major> bf;
                wmma::load_matrix_sync(bf, Bs + kk * B_LD + wn + j * 16, B_LD);
                #pragma unroll
                for (int i = 0; i < 4; i++)
                    wmma::mma_sync(acc[i][j], af[i], bf, acc[i][j]);
            }
        }

        CP_WAIT0();
        __syncthreads();
    }

    // ---- epilogue: stage fp32 per warp (16x64 chunks), add bias, write ----
    float* fbuf = (float*)smem + warp * 16 * C_LD;
    const float* brow = bias + bn + wn;
    #pragma unroll
    for (int i = 0; i < 4; i++) {
        #pragma unroll
        for (int j = 0; j < 4; j++)
            wmma::store_matrix_sync(fbuf + j * 16, acc[i][j], C_LD, wmma::mem_row_major);
        __syncwarp();
        #pragma unroll
        for (int ii = 0; ii < 8; ii++) {
            int idx4 = lane + 32 * ii;          // 256 float4 = 16x64
            int row  = idx4 >> 4;
            int col  = (idx4 & 15) * 4;
            float4 v = *(float4*)(fbuf + row * C_LD + col);
            float4 b4 = *(const float4*)(brow + col);
            v.x += b4.x; v.y += b4.y; v.z += b4.z; v.w += b4.w;
            *(float4*)(out + (size_t)(bm + wm + i * 16 + row) * N_OUT + bn + wn + col) = v;
        }
        __syncwarp();
    }
}

// ---------------------------------------------------------------------------
// Launch.  Inputs: x(f32), qweight(i32), qzeros(i32), scales(f32), g_idx(i32),
//                  bias(f32).  Output f32 [M_TOK, N_OUT].
// ---------------------------------------------------------------------------
extern "C" void kernel_launch(void* const* d_in, const int* in_sizes, int n_in,
                              void* d_out, int out_size)
{
    const float* x       = (const float*)d_in[0];
    const int*   qweight = (const int*)d_in[1];
    const int*   qzeros  = (const int*)d_in[2];
    const float* scales  = (const float*)d_in[3];
    const float* bias    = (const float*)d_in[5];
    float* out = (float*)d_out;

    {
        size_t n4 = (size_t)M_TOK * K_IN / 4;
        convert_x_kernel<<<(unsigned)((n4 + 255) / 256), 256>>>(x);
    }
    {
        cudaFuncSetAttribute(gemm_q4_kernel,
                             cudaFuncAttributeMaxDynamicSharedMemorySize,
                             SMEM_DYN);
        dim3 grid(M_TOK / BM, N_OUT / BN);   // (32, 86), M fastest
        gemm_q4_kernel<<<grid, NTHREADS, SMEM_DYN>>>(qweight, qzeros, scales, bias, out);
    }
}